// round 17
// baseline (speedup 1.0000x reference)
#include <cuda_runtime.h>
#include <cstdint>

#define S_LEN 2048
#define NH    16
#define HD    64
#define NTHR  128
#define SCALE 0.1875f   // 1.5 / sqrt(64)

#define KS 68
#define VS 72
#define AS 68
// Ks[64*68] | Vs[64*72] | At[64*68]  — single-buffered, 53.2 KB => 4 CTAs/SM
#define SMEM_FLOATS (64*KS + 64*VS + 64*AS)

// split-K scratch: 32 (h,b) x 16 split ranks (tt=16..31)
__device__ float g_OB[32 * 16 * 64 * 64];   // lower-half partial O (8 MB)
__device__ float g_RA[32 * 16 * 64];        // upper-half remainder products
__device__ float g_RB[32 * 16 * 64];        // lower-half remainder products

// 48 jobs per (h,b), descending size: {tt, kt_hi, kt_lo, mode} mode:0=full,1=upper,2=lower
__constant__ uchar4 job_tbl[48] = {
    {31,31,16,1},{31,15, 0,2},{30,30,15,1},{15,15, 0,0},
    {30,14, 0,2},{29,29,15,1},{29,14, 0,2},{28,28,14,1},{14,14, 0,0},
    {28,13, 0,2},{27,27,14,1},{27,13, 0,2},{26,26,13,1},{13,13, 0,0},
    {26,12, 0,2},{25,25,13,1},{25,12, 0,2},{24,24,12,1},{12,12, 0,0},
    {24,11, 0,2},{23,23,12,1},{23,11, 0,2},{22,22,11,1},{11,11, 0,0},
    {22,10, 0,2},{21,21,11,1},{21,10, 0,2},{20,20,10,1},{10,10, 0,0},
    {20, 9, 0,2},{19,19,10,1},{19, 9, 0,2},{18,18, 9,1},{ 9, 9, 0,0},
    {18, 8, 0,2},{17,17, 9,1},{17, 8, 0,2},{16,16, 8,1},{ 8, 8, 0,0},
    {16, 7, 0,2},
    { 7, 7, 0,0},{ 6, 6, 0,0},{ 5, 5, 0,0},{ 4, 4, 0,0},
    { 3, 3, 0,0},{ 2, 2, 0,0},{ 1, 1, 0,0},{ 0, 0, 0,0}
};

__device__ __forceinline__ uint32_t f2tf(float x) {
    uint32_t r; asm("cvt.rna.tf32.f32 %0, %1;" : "=r"(r) : "f"(x)); return r;
}

__device__ __forceinline__ void cp16(uint32_t saddr, const float* g) {
    asm volatile("cp.async.cg.shared.global [%0], [%1], 16;" :: "r"(saddr), "l"(g) : "memory");
}

__device__ __forceinline__ void ldsm_x4(uint32_t& r0, uint32_t& r1, uint32_t& r2, uint32_t& r3,
                                        uint32_t saddr) {
    asm volatile("ldmatrix.sync.aligned.m8n8.x4.shared.b16 {%0,%1,%2,%3}, [%4];"
                 : "=r"(r0), "=r"(r1), "=r"(r2), "=r"(r3) : "r"(saddr));
}

__device__ __forceinline__ void mma_tf32(float& d0, float& d1, float& d2, float& d3,
                                         uint32_t a0, uint32_t a1, uint32_t a2, uint32_t a3,
                                         uint32_t b0, uint32_t b1) {
    asm volatile("mma.sync.aligned.m16n8k8.row.col.f32.tf32.tf32.f32 "
                 "{%0,%1,%2,%3}, {%4,%5,%6,%7}, {%8,%9}, {%0,%1,%2,%3};"
                 : "+f"(d0), "+f"(d1), "+f"(d2), "+f"(d3)
                 : "r"(a0), "r"(a1), "r"(a2), "r"(a3), "r"(b0), "r"(b1));
}

template<bool MASKED>
__device__ __forceinline__ void sig_pair_t(float x, bool mask, float& sg, float& om) {
    const float t = __expf(-fabsf(x));
    const float r = __fdividef(1.f, 1.f + t);
    const float tr = t * r;
    const bool pos = x >= 0.f;
    if (MASKED) {
        sg = mask ? (pos ? r : tr) : 0.f;
        om = mask ? (pos ? tr : r) : 1.f;
    } else {
        sg = pos ? r : tr;
        om = pos ? tr : r;
    }
}

struct ScanCtx {
    int s0, tg_lo, tg_hi, m0, gp, qd;
    float* At;
};

template<bool MASKED>
__device__ __forceinline__ void scan_j(const float dj[4], int j, const ScanCtx& c,
                                       float& R_lo, float& R_hi)
{
    bool m00 = true, m01 = true, m10 = true, m11 = true;
    if (MASKED) {
        const int sg0 = c.s0 + j * 8 + 2 * c.qd;
        m00 = sg0     < c.tg_lo; m01 = sg0 + 1 < c.tg_lo;
        m10 = sg0     < c.tg_hi; m11 = sg0 + 1 < c.tg_hi;
    }

    float sg00, om00, sg01, om01, sg10, om10, sg11, om11;
    sig_pair_t<MASKED>(dj[0], m00, sg00, om00);
    sig_pair_t<MASKED>(dj[1], m01, sg01, om01);
    sig_pair_t<MASKED>(dj[2], m10, sg10, om10);
    sig_pair_t<MASKED>(dj[3], m11, sg11, om11);

    const float bs_lo = om00 * om01;
    const float bs_hi = om10 * om11;

    float i_lo = bs_lo, i_hi = bs_hi, u;
    u = __shfl_down_sync(0xffffffffu, i_lo, 1, 4); if (c.qd < 3) i_lo *= u;
    u = __shfl_down_sync(0xffffffffu, i_hi, 1, 4); if (c.qd < 3) i_hi *= u;
    u = __shfl_down_sync(0xffffffffu, i_lo, 2, 4); if (c.qd < 2) i_lo *= u;
    u = __shfl_down_sync(0xffffffffu, i_hi, 2, 4); if (c.qd < 2) i_hi *= u;

    float ex_lo = __shfl_down_sync(0xffffffffu, i_lo, 1, 4);
    float ex_hi = __shfl_down_sync(0xffffffffu, i_hi, 1, 4);
    if (c.qd == 3) { ex_lo = 1.f; ex_hi = 1.f; }
    const float T_lo = __shfl_sync(0xffffffffu, i_lo, 0, 4);
    const float T_hi = __shfl_sync(0xffffffffu, i_hi, 0, 4);

    const float E_lo = ex_lo * R_lo;
    const float E_hi = ex_hi * R_hi;

    *(float2*)&c.At[(c.m0 + c.gp)     * AS + j * 8 + 2 * c.qd] =
        make_float2(__uint_as_float(f2tf(sg00 * om01 * E_lo)),
                    __uint_as_float(f2tf(sg01 * E_lo)));
    *(float2*)&c.At[(c.m0 + c.gp + 8) * AS + j * 8 + 2 * c.qd] =
        make_float2(__uint_as_float(f2tf(sg10 * om11 * E_hi)),
                    __uint_as_float(f2tf(sg11 * E_hi)));

    R_lo *= T_lo;
    R_hi *= T_hi;
}

__device__ __forceinline__ void qk_pair(float dlo[4], float dhi[4], uint32_t k_lm, int p,
                                        const uint32_t qa[8][4])
{
    #pragma unroll
    for (int c = 0; c < 4; c++) { dlo[c] = 0.f; dhi[c] = 0.f; }
    #pragma unroll
    for (int ks = 0; ks < 8; ks++) {
        uint32_t b0a, b1a, b0b, b1b;
        ldsm_x4(b0a, b1a, b0b, b1b, k_lm + 4u * (uint32_t)(p * 16 * KS + 8 * ks));
        mma_tf32(dlo[0], dlo[1], dlo[2], dlo[3],
                 qa[ks][0], qa[ks][1], qa[ks][2], qa[ks][3], b0a, b1a);
        mma_tf32(dhi[0], dhi[1], dhi[2], dhi[3],
                 qa[ks][0], qa[ks][1], qa[ks][2], qa[ks][3], b0b, b1b);
    }
}

template<bool MASKED>
__device__ __forceinline__ void tile_compute(
    int kt, int kt_lo, const ScanCtx& ctx, const uint32_t qa[8][4],
    uint32_t k_lm, uint32_t at_lm_base, const float* Vs,
    uint32_t s_k, const float* __restrict__ qkv, int b, int h, int r0, int c0,
    float o[8][4], float& R_lo, float& R_hi)
{
    float d[8][4];
    qk_pair(d[6], d[7], k_lm, 3, qa);
    qk_pair(d[4], d[5], k_lm, 2, qa);
    scan_j<MASKED>(d[7], 7, ctx, R_lo, R_hi);
    scan_j<MASKED>(d[6], 6, ctx, R_lo, R_hi);
    qk_pair(d[2], d[3], k_lm, 1, qa);
    scan_j<MASKED>(d[5], 5, ctx, R_lo, R_hi);
    scan_j<MASKED>(d[4], 4, ctx, R_lo, R_hi);
    qk_pair(d[0], d[1], k_lm, 0, qa);

    __syncthreads();   // B2: all warps done reading Ks -> buffer reusable

    if (kt > kt_lo) {
        const int s0n = (kt - 1) * 64;
        const float* kg = qkv + (((size_t)b * S_LEN + (s0n + r0)) * 3 + 1) * (NH * HD) + h * HD + c0;
        #pragma unroll
        for (int p = 0; p < 8; p++)
            cp16(s_k + (uint32_t)((r0 + 8 * p) * KS + c0) * 4u, kg + (size_t)p * 8 * 3 * NH * HD);
        asm volatile("cp.async.commit_group;" ::: "memory");
    }

    scan_j<MASKED>(d[3], 3, ctx, R_lo, R_hi);
    scan_j<MASKED>(d[2], 2, ctx, R_lo, R_hi);
    scan_j<MASKED>(d[1], 1, ctx, R_lo, R_hi);
    scan_j<MASKED>(d[0], 0, ctx, R_lo, R_hi);

    if (kt > kt_lo) { asm volatile("cp.async.wait_group 1;" ::: "memory"); }
    else            { asm volatile("cp.async.wait_group 0;" ::: "memory"); }
    __syncthreads();   // B3: V visible; At stores ordered for cross-lane ldmatrix

    const int gp = ctx.gp, qd = ctx.qd;
    #pragma unroll
    for (int ks = 0; ks < 8; ks++) {
        const int kc = ks * 8;
        uint32_t a0, a1, a2, a3;
        ldsm_x4(a0, a1, a2, a3, at_lm_base + 32u * (uint32_t)ks);
        #pragma unroll
        for (int j = 0; j < 8; j++) {
            uint32_t b0 = __float_as_uint(Vs[(kc + qd)     * VS + j * 8 + gp]);
            uint32_t b1 = __float_as_uint(Vs[(kc + qd + 4) * VS + j * 8 + gp]);
            mma_tf32(o[j][0], o[j][1], o[j][2], o[j][3], a0, a1, a2, a3, b0, b1);
        }
    }
}

__global__ void __launch_bounds__(NTHR, 4)
sb_attn_kernel(const float* __restrict__ qkv, float* __restrict__ out)
{
    extern __shared__ float smem[];
    float* Ks = smem;
    float* Vs = Ks + 64 * KS;
    float* At = Vs + 64 * VS;

    const int hb = (int)blockIdx.x;            // 0..31 (fast dim)
    const int h  = hb & 15;
    const int b  = hb >> 4;
    const uchar4 job = job_tbl[blockIdx.y];    // descending-size order (LPT)
    const int tt     = job.x;
    const int kt_hi  = job.y;
    const int kt_lo  = job.z;
    const int mode   = job.w;                  // 0=full, 1=upper, 2=lower

    const int tid  = threadIdx.x;
    const int warp = tid >> 5;
    const int lane = tid & 31;
    const int gp   = lane >> 2;
    const int qd   = lane & 3;
    const int m0   = warp * 16;
    const int t0   = tt * 64;

    const int tg_lo = t0 + m0 + gp;
    const int tg_hi = tg_lo + 8;

    const uint32_t s_k  = (uint32_t)__cvta_generic_to_shared(Ks);
    const uint32_t s_v  = (uint32_t)__cvta_generic_to_shared(Vs);
    const uint32_t s_at = (uint32_t)__cvta_generic_to_shared(At);

    const int mat  = lane >> 3;
    const int mrow = lane & 7;
    const uint32_t k_lm = s_k + 4u * ((uint32_t)(((mat >> 1) * 8 + mrow) * KS) + (uint32_t)((mat & 1) * 4));
    const uint32_t at_lm_base = s_at + 4u * ((uint32_t)((m0 + (mat & 1) * 8 + mrow) * AS) + (uint32_t)((mat >> 1) * 4));

    const int r0 = tid >> 4;
    const int c0 = (tid & 15) * 4;

    // ---- Q fragments in registers ----
    uint32_t qa[8][4];
    {
        const float* qlo = qkv + (((size_t)b * S_LEN + tg_lo) * 3 + 0) * (NH * HD) + h * HD;
        const float* qhi = qkv + (((size_t)b * S_LEN + tg_hi) * 3 + 0) * (NH * HD) + h * HD;
        #pragma unroll
        for (int ks = 0; ks < 8; ks++) {
            qa[ks][0] = f2tf(SCALE * qlo[ks * 8 + qd]);
            qa[ks][1] = f2tf(SCALE * qhi[ks * 8 + qd]);
            qa[ks][2] = f2tf(SCALE * qlo[ks * 8 + qd + 4]);
            qa[ks][3] = f2tf(SCALE * qhi[ks * 8 + qd + 4]);
        }
    }

    // ---- Prologue: async-load top K tile of this job's range ----
    {
        const float* kg = qkv + (((size_t)b * S_LEN + (kt_hi * 64 + r0)) * 3 + 1) * (NH * HD) + h * HD + c0;
        #pragma unroll
        for (int p = 0; p < 8; p++)
            cp16(s_k + (uint32_t)((r0 + 8 * p) * KS + c0) * 4u, kg + (size_t)p * 8 * 3 * NH * HD);
        asm volatile("cp.async.commit_group;" ::: "memory");
    }

    float o[8][4];
    #pragma unroll
    for (int j = 0; j < 8; j++)
        #pragma unroll
        for (int c = 0; c < 4; c++) o[j][c] = 0.f;
    float R_lo = 1.f, R_hi = 1.f;

    for (int kt = kt_hi; kt >= kt_lo; --kt) {
        asm volatile("cp.async.wait_group 0;" ::: "memory");
        __syncthreads();   // B1

        const int s0 = kt * 64;
        {
            const float* vg = qkv + (((size_t)b * S_LEN + (s0 + r0)) * 3 + 2) * (NH * HD) + h * HD + c0;
            #pragma unroll
            for (int p = 0; p < 8; p++)
                cp16(s_v + (uint32_t)((r0 + 8 * p) * VS + c0) * 4u, vg + (size_t)p * 8 * 3 * NH * HD);
            asm volatile("cp.async.commit_group;" ::: "memory");
        }

        ScanCtx ctx{s0, tg_lo, tg_hi, m0, gp, qd, At};

        if (kt == tt) {
            tile_compute<true >(kt, kt_lo, ctx, qa, k_lm, at_lm_base, Vs, s_k, qkv, b, h, r0, c0,
                                o, R_lo, R_hi);
        } else {
            tile_compute<false>(kt, kt_lo, ctx, qa, k_lm, at_lm_base, Vs, s_k, qkv, b, h, r0, c0,
                                o, R_lo, R_hi);
        }
    }

    // ---- Epilogue by mode ----
    if (mode == 2) {
        // lower half: write partial O and R_B to scratch
        const int idx = tt - 16;
        float* ob = g_OB + ((size_t)(hb * 16 + idx) * 64) * 64;
        #pragma unroll
        for (int j = 0; j < 8; j++) {
            const int n0 = j * 8 + 2 * qd;
            *(float2*)&ob[(m0 + gp)     * 64 + n0] = make_float2(o[j][0], o[j][1]);
            *(float2*)&ob[(m0 + gp + 8) * 64 + n0] = make_float2(o[j][2], o[j][3]);
        }
        if (qd == 0) {
            g_RB[(hb * 16 + idx) * 64 + m0 + gp]     = R_lo;
            g_RB[(hb * 16 + idx) * 64 + m0 + gp + 8] = R_hi;
        }
    } else {
        // full: out = O + rem*v ;  upper: out = O, save R_A
        const float rem_lo = (mode == 0) ? R_lo : 0.f;
        const float rem_hi = (mode == 0) ? R_hi : 0.f;
        if (mode == 1 && qd == 0) {
            const int idx = tt - 16;
            g_RA[(hb * 16 + idx) * 64 + m0 + gp]     = R_lo;
            g_RA[(hb * 16 + idx) * 64 + m0 + gp + 8] = R_hi;
        }
        #pragma unroll
        for (int j = 0; j < 8; j++) {
            const int n0 = j * 8 + 2 * qd;
            const float* vpa = qkv + (((size_t)b * S_LEN + tg_lo) * 3 + 2) * (NH * HD) + h * HD + n0;
            const float* vpb = qkv + (((size_t)b * S_LEN + tg_hi) * 3 + 2) * (NH * HD) + h * HD + n0;
            float2 va = *(const float2*)vpa;
            float2 vb = *(const float2*)vpb;
            float2 oa = make_float2(o[j][0] + rem_lo * va.x, o[j][1] + rem_lo * va.y);
            float2 ob = make_float2(o[j][2] + rem_hi * vb.x, o[j][3] + rem_hi * vb.y);
            *(float2*)(out + (((size_t)b * S_LEN + tg_lo) * NH + h) * HD + n0) = oa;
            *(float2*)(out + (((size_t)b * S_LEN + tg_hi) * NH + h) * HD + n0) = ob;
        }
    }
}

// combine: out += R_A * (O_B + R_B * v)   for split ranks (tt = 16..31)
__global__ void __launch_bounds__(256)
sb_combine_kernel(const float* __restrict__ qkv, float* __restrict__ out)
{
    const int hb  = (int)blockIdx.x;   // 0..31
    const int idx = (int)blockIdx.y;   // 0..15 -> tt = idx+16
    const int h   = hb & 15;
    const int b   = hb >> 4;
    const int t0  = (idx + 16) * 64;
    const int tid = threadIdx.x;

    const float* ob_base = g_OB + ((size_t)(hb * 16 + idx) * 64) * 64;
    const float* ra_base = g_RA + (hb * 16 + idx) * 64;
    const float* rb_base = g_RB + (hb * 16 + idx) * 64;

    #pragma unroll
    for (int i = tid; i < 64 * 32; i += 256) {
        const int row = i >> 5;
        const int c2  = (i & 31) * 2;
        const float ra = ra_base[row];
        const float rb = rb_base[row];
        const float2 obv = *(const float2*)&ob_base[row * 64 + c2];
        const float2 v   = *(const float2*)(qkv + (((size_t)b * S_LEN + t0 + row) * 3 + 2) * (NH * HD) + h * HD + c2);
        float2* op = (float2*)(out + (((size_t)b * S_LEN + t0 + row) * NH + h) * HD + c2);
        float2 cur = *op;
        cur.x += ra * (obv.x + rb * v.x);
        cur.y += ra * (obv.y + rb * v.y);
        *op = cur;
    }
}

extern "C" void kernel_launch(void* const* d_in, const int* in_sizes, int n_in,
                              void* d_out, int out_size)
{
    const float* qkv = (const float*)d_in[0];
    float* out = (float*)d_out;

    cudaFuncSetAttribute(sb_attn_kernel,
                         cudaFuncAttributeMaxDynamicSharedMemorySize,
                         SMEM_FLOATS * sizeof(float));

    dim3 grid(NH * 2, 48, 1);   // x = (h,b) fast, y = LPT job order
    sb_attn_kernel<<<grid, NTHR, SMEM_FLOATS * sizeof(float)>>>(qkv, out);

    dim3 cgrid(NH * 2, 16, 1);
    sb_combine_kernel<<<cgrid, 256>>>(qkv, out);
}